// round 3
// baseline (speedup 1.0000x reference)
#include <cuda_runtime.h>
#include <cuda_bf16.h>
#include <math.h>

// Problem constants
#define NF   16384
#define HID  64
#define TH   192          // 3*HID
#define FPB  16           // features per block
#define NBLK (NF / FPB)   // 1024

// Static scratch (no dynamic allocation allowed)
__device__ float g_partial_agg[NBLK * HID];   // per-block masked sums of h_gate
__device__ int   g_partial_cnt[NBLK];         // per-block mask counts
__device__ int   g_total_cnt;                 // written by finalize, read by fixup

// ---------------------------------------------------------------------------
// mask representation detection: 0 = uint8 (bool), 1 = int32, 2 = float32
// mask values are only 0/1; random pattern disambiguates byte layout.
// ---------------------------------------------------------------------------
__device__ __forceinline__ int detect_mask_mode(const void* mp) {
    const unsigned int* w = (const unsigned int*)mp;
    #pragma unroll 1
    for (int i = 0; i < 64; i++) {
        if (w[i] == 0x3F800000u) return 2;           // float 1.0 seen -> f32
    }
    const unsigned char* p = (const unsigned char*)mp;
    #pragma unroll 1
    for (int i = 0; i < 256; i++) {
        if ((i & 3) != 0 && p[i] != 0) return 0;     // nonzero off-aligned byte -> u8
    }
    return 1;                                         // int32 0/1
}

__device__ __forceinline__ bool mask_at(const void* mp, int mode, int f) {
    if (mode == 0) return ((const unsigned char*)mp)[f] != 0;
    if (mode == 1) return ((const int*)mp)[f] != 0;
    return ((const float*)mp)[f] != 0.0f;
}

// ---------------------------------------------------------------------------
// Kernel 1: per-feature GRU cell + block-local masked aggregation.
// grid = NBLK blocks, 192 threads. Each block handles FPB consecutive features.
// ---------------------------------------------------------------------------
__global__ __launch_bounds__(TH) void gru_main_kernel(
    const float* __restrict__ X,
    const void*  __restrict__ mask,
    const float* __restrict__ Ht,
    const float* __restrict__ xT_w,   // (F, 192, 1)
    const float* __restrict__ xT_b,   // (F, 192)
    const float* __restrict__ U_w,    // (F, 192, 64)
    float*       __restrict__ H_curr) // (F, 64)  == d_out + 2
{
    __shared__ float sHt[HID];
    __shared__ float sU[TH];
    __shared__ float sX[TH];
    __shared__ float sAgg[HID];
    __shared__ int   sMode;

    const int t = threadIdx.x;
    const int b = blockIdx.x;

    if (t == 0) sMode = detect_mask_mode(mask);
    if (t < HID) sAgg[t] = 0.0f;
    int cnt = 0;

    for (int j = 0; j < FPB; j++) {
        const int f = b * FPB + j;

        if (t < HID) sHt[t] = Ht[f * HID + t];
        __syncthreads();

        // u = dot(U_w[f, t, :], Ht[f, :])   -- 16 fully-unrolled LDG.128
        const float4* __restrict__ row =
            reinterpret_cast<const float4*>(U_w + ((size_t)f * TH + t) * HID);
        const float4* hs = reinterpret_cast<const float4*>(sHt);
        float a0 = 0.f, a1 = 0.f, a2 = 0.f, a3 = 0.f;
        #pragma unroll
        for (int k = 0; k < 16; k += 4) {
            float4 v0 = row[k + 0], v1 = row[k + 1], v2 = row[k + 2], v3 = row[k + 3];
            float4 h0 = hs[k + 0],  h1 = hs[k + 1],  h2 = hs[k + 2],  h3 = hs[k + 3];
            a0 += v0.x * h0.x + v0.y * h0.y + v0.z * h0.z + v0.w * h0.w;
            a1 += v1.x * h1.x + v1.y * h1.y + v1.z * h1.z + v1.w * h1.w;
            a2 += v2.x * h2.x + v2.y * h2.y + v2.z * h2.z + v2.w * h2.w;
            a3 += v3.x * h3.x + v3.y * h3.y + v3.z * h3.z + v3.w * h3.w;
        }
        sU[t] = (a0 + a1) + (a2 + a3);
        sX[t] = xT_w[(size_t)f * TH + t] * X[f] + xT_b[(size_t)f * TH + t];
        __syncthreads();

        if (t < HID) {
            const float z  = 1.0f / (1.0f + __expf(-(sX[t]           + sU[t])));
            const float r  = 1.0f / (1.0f + __expf(-(sX[t + HID]     + sU[t + HID])));
            const float htl = tanhf(sX[t + 2 * HID] + r * sU[t + 2 * HID]);
            const float hg = z * sHt[t] + (1.0f - z) * htl;

            const bool m = mask_at(mask, sMode, f);
            H_curr[(size_t)f * HID + t] = m ? hg : 0.0f;
            if (m) sAgg[t] += hg;
            if (t == 0) cnt += (int)m;
        }
        __syncthreads();   // protect sHt/sU/sX for next iteration
    }

    if (t < HID) g_partial_agg[b * HID + t] = sAgg[t];
    if (t == 0)  g_partial_cnt[b] = cnt;
}

// ---------------------------------------------------------------------------
// Kernel 2: reduce partials, MLP head, softmax -> pred (d_out[0..1]).
// Single block, 64 threads.
// ---------------------------------------------------------------------------
__global__ __launch_bounds__(HID) void finalize_kernel(
    const float* __restrict__ W1,  // (64, 64)
    const float* __restrict__ b1,  // (64,)
    const float* __restrict__ W2,  // (64, 2)
    const float* __restrict__ b2,  // (2,)
    float*       __restrict__ out) // d_out
{
    __shared__ float sAgg[HID];
    __shared__ float sHid[HID];
    __shared__ int   sCnt[HID];

    const int t = threadIdx.x;

    // reduce per-block partials
    float a = 0.0f;
    int   c = 0;
    #pragma unroll 4
    for (int b = 0; b < NBLK; b++) a += g_partial_agg[b * HID + t];
    for (int b = t; b < NBLK; b += HID) c += g_partial_cnt[b];
    sCnt[t] = c;
    __syncthreads();

    // total count (tree reduce in shared)
    for (int s = HID / 2; s > 0; s >>= 1) {
        if (t < s) sCnt[t] += sCnt[t + s];
        __syncthreads();
    }
    const int total = sCnt[0];
    if (t == 0) g_total_cnt = total;

    const float denom = fmaxf((float)total, 1.0f);
    sAgg[t] = a / denom;
    __syncthreads();

    // hid = relu(agg @ W1 + b1)
    float acc = b1[t];
    #pragma unroll 8
    for (int k = 0; k < HID; k++) acc += sAgg[k] * W1[k * HID + t];
    sHid[t] = fmaxf(acc, 0.0f);
    __syncthreads();

    // logits = hid @ W2 + b2 ; softmax over the 2 classes
    if (t == 0) {
        float l0 = b2[0], l1 = b2[1];
        #pragma unroll 8
        for (int j = 0; j < HID; j++) {
            l0 += sHid[j] * W2[j * 2 + 0];
            l1 += sHid[j] * W2[j * 2 + 1];
        }
        const float mx = fmaxf(l0, l1);
        const float e0 = expf(l0 - mx), e1 = expf(l1 - mx);
        const float inv = 1.0f / (e0 + e1);
        out[0] = e0 * inv;
        out[1] = e1 * inv;
    }
}

// ---------------------------------------------------------------------------
// Kernel 3: if no feature is masked, H_curr = Ht (reference's where(any(mask))).
// Early-exits in the common case (count > 0).
// ---------------------------------------------------------------------------
__global__ void fixup_kernel(const float* __restrict__ Ht,
                             float*       __restrict__ H_curr)
{
    if (g_total_cnt > 0) return;
    const int total = NF * HID;
    for (int i = blockIdx.x * blockDim.x + threadIdx.x; i < total;
         i += gridDim.x * blockDim.x) {
        H_curr[i] = Ht[i];
    }
}

// ---------------------------------------------------------------------------
// Launch.  Input order (metadata): tim, X, X_hap, mask, Ht, xT_w, xT_b, U_w,
//                                  W1, b1, W2, b2.
// Output: [pred(2), H_curr(16384*64)] float32.
// ---------------------------------------------------------------------------
extern "C" void kernel_launch(void* const* d_in, const int* in_sizes, int n_in,
                              void* d_out, int out_size)
{
    const float* X     = (const float*)d_in[1];
    const void*  mask  = d_in[3];
    const float* Ht    = (const float*)d_in[4];
    const float* xT_w  = (const float*)d_in[5];
    const float* xT_b  = (const float*)d_in[6];
    const float* U_w   = (const float*)d_in[7];
    const float* W1    = (const float*)d_in[8];
    const float* b1    = (const float*)d_in[9];
    const float* W2    = (const float*)d_in[10];
    const float* b2    = (const float*)d_in[11];

    float* out    = (float*)d_out;
    float* H_curr = out + 2;

    gru_main_kernel<<<NBLK, TH>>>(X, mask, Ht, xT_w, xT_b, U_w, H_curr);
    finalize_kernel<<<1, HID>>>(W1, b1, W2, b2, out);
    fixup_kernel<<<64, 256>>>(Ht, H_curr);
}

// round 7
// speedup vs baseline: 1.1978x; 1.1978x over previous
#include <cuda_runtime.h>
#include <cuda_bf16.h>
#include <math.h>

// Problem constants
#define NF   16384
#define HID  64
#define TH   192          // 3*HID rows of U per feature
#define FPB  8            // features per block
#define NBLK (NF / FPB)   // 2048
#define ROWB 272          // padded row bytes in SMEM (68 floats) -> conflict-free LDS.128
#define U_STAGE (TH * ROWB)   // 52224 bytes

// Dynamic shared memory layout (bytes)
#define OFF_U0   0
#define OFF_U1   52224
#define OFF_HT   104448   // 2 stages x 64 floats (256B each)
#define OFF_XW   104960   // 2 stages x 192 floats (768B each)
#define OFF_XB   106496   // 2 stages x 192 floats
#define OFF_XF   108032   // 2 stages x 1 float
#define OFF_SU   108048   // 192 floats
#define OFF_SX   108816   // 192 floats
#define OFF_MODE 109584   // int
#define SMEM_TOTAL 109600

// Static scratch
__device__ float g_partial_agg[NBLK * HID];
__device__ int   g_partial_cnt[NBLK];
__device__ int   g_total_cnt;

// ---------------------------------------------------------------------------
// helpers
// ---------------------------------------------------------------------------
__device__ __forceinline__ unsigned smem_u32(const void* p) {
    return (unsigned)__cvta_generic_to_shared(p);
}
#define CP16(dst, src) asm volatile("cp.async.cg.shared.global [%0], [%1], 16;" :: "r"(dst), "l"(src))
#define CP4(dst, src)  asm volatile("cp.async.ca.shared.global [%0], [%1], 4;"  :: "r"(dst), "l"(src))
#define CPCOMMIT()     asm volatile("cp.async.commit_group;")
#define CPWAIT1()      asm volatile("cp.async.wait_group 1;" ::: "memory")

// mask representation detection: 0 = uint8 (bool), 1 = int32, 2 = float32
__device__ __forceinline__ int detect_mask_mode(const void* mp) {
    const unsigned int* w = (const unsigned int*)mp;
    #pragma unroll 1
    for (int i = 0; i < 64; i++) {
        if (w[i] == 0x3F800000u) return 2;
    }
    const unsigned char* p = (const unsigned char*)mp;
    #pragma unroll 1
    for (int i = 0; i < 256; i++) {
        if ((i & 3) != 0 && p[i] != 0) return 0;
    }
    return 1;
}

__device__ __forceinline__ bool mask_at(const void* mp, int mode, int f) {
    if (mode == 0) return ((const unsigned char*)mp)[f] != 0;
    if (mode == 1) return ((const int*)mp)[f] != 0;
    return ((const float*)mp)[f] != 0.0f;
}

// ---------------------------------------------------------------------------
// cp.async stage of one feature: U_w tile (48KB, padded rows), xT_w, xT_b,
// Ht, X[f]. Global side fully coalesced, L1-bypassing (.cg for 16B chunks).
// ---------------------------------------------------------------------------
__device__ __forceinline__ void issue_feature(
    unsigned sb, int s, int f, int t,
    const float* __restrict__ U_w, const float* __restrict__ Ht,
    const float* __restrict__ xT_w, const float* __restrict__ xT_b,
    const float* __restrict__ X)
{
    const unsigned ub = sb + (s ? OFF_U1 : OFF_U0);
    const char* g = (const char*)(U_w + (size_t)f * TH * HID);
    #pragma unroll
    for (int k = 0; k < 16; k++) {
        const int c = t + TH * k;             // 16B chunk index, 0..3071
        const unsigned dst = ub + (unsigned)(c >> 4) * ROWB + (unsigned)(c & 15) * 16u;
        CP16(dst, g + (size_t)c * 16);
    }
    if (t < 48) {
        CP16(sb + OFF_XW + s * 768 + t * 16, (const char*)(xT_w + (size_t)f * TH) + t * 16);
    } else if (t < 96) {
        const int u = t - 48;
        CP16(sb + OFF_XB + s * 768 + u * 16, (const char*)(xT_b + (size_t)f * TH) + u * 16);
    } else if (t < 112) {
        const int u = t - 96;
        CP16(sb + OFF_HT + s * 256 + u * 16, (const char*)(Ht + (size_t)f * HID) + u * 16);
    } else if (t == 112) {
        CP4(sb + OFF_XF + s * 4, (const char*)(X + f));
    }
}

// ---------------------------------------------------------------------------
// Kernel 1: per-feature GRU cell, double-buffered cp.async pipeline.
// grid = NBLK, 192 threads (thread t owns U row t of each feature).
// ---------------------------------------------------------------------------
extern __shared__ char smem[];
__global__ __launch_bounds__(TH) void gru_main_kernel(
    const float* __restrict__ X,
    const void*  __restrict__ mask,
    const float* __restrict__ Ht,
    const float* __restrict__ xT_w,
    const float* __restrict__ xT_b,
    const float* __restrict__ U_w,
    float*       __restrict__ H_curr)
{
    const int t  = threadIdx.x;
    const int b  = blockIdx.x;
    const int f0 = b * FPB;
    const unsigned sb = smem_u32(smem);

    if (t == 0) *(int*)(smem + OFF_MODE) = detect_mask_mode(mask);

    issue_feature(sb, 0, f0 + 0, t, U_w, Ht, xT_w, xT_b, X); CPCOMMIT();
    issue_feature(sb, 1, f0 + 1, t, U_w, Ht, xT_w, xT_b, X); CPCOMMIT();

    float aggv = 0.0f;
    int   cnt  = 0;

    #pragma unroll 1
    for (int j = 0; j < FPB; j++) {
        const int s = j & 1;
        const int f = f0 + j;

        CPWAIT1();              // feature j's group complete (j+1 still pending)
        __syncthreads();        // all threads' stage-s data visible

        const int mode = *(const int*)(smem + OFF_MODE);
        bool mv = false;
        if (t < HID) mv = mask_at(mask, mode, f);   // early LDG, 1 line broadcast

        // dot(U_row[t], Ht) from SMEM — conflict-free LDS.128 (272B row stride)
        const float4* __restrict__ Ur =
            (const float4*)(smem + (s ? OFF_U1 : OFF_U0) + t * ROWB);
        const float4* __restrict__ Hs = (const float4*)(smem + OFF_HT + s * 256);
        float a0 = 0.f, a1 = 0.f, a2 = 0.f, a3 = 0.f;
        #pragma unroll
        for (int k = 0; k < 16; k += 4) {
            float4 v0 = Ur[k + 0], v1 = Ur[k + 1], v2 = Ur[k + 2], v3 = Ur[k + 3];
            float4 h0 = Hs[k + 0], h1 = Hs[k + 1], h2 = Hs[k + 2], h3 = Hs[k + 3];
            a0 += v0.x * h0.x + v0.y * h0.y + v0.z * h0.z + v0.w * h0.w;
            a1 += v1.x * h1.x + v1.y * h1.y + v1.z * h1.z + v1.w * h1.w;
            a2 += v2.x * h2.x + v2.y * h2.y + v2.z * h2.z + v2.w * h2.w;
            a3 += v3.x * h3.x + v3.y * h3.y + v3.z * h3.z + v3.w * h3.w;
        }
        const float dot = (a0 + a1) + (a2 + a3);

        const float xwv = ((const float*)(smem + OFF_XW + s * 768))[t];
        const float xbv = ((const float*)(smem + OFF_XB + s * 768))[t];
        const float xfv = *(const float*)(smem + OFF_XF + s * 4);
        float htv = 0.0f;
        if (t < HID) htv = ((const float*)(smem + OFF_HT + s * 256))[t]; // capture before refill

        ((float*)(smem + OFF_SU))[t] = dot;
        ((float*)(smem + OFF_SX))[t] = fmaf(xwv, xfv, xbv);
        __syncthreads();        // stage-s reads done + sU/sX published

        if (j + 2 < FPB)
            issue_feature(sb, s, f + 2, t, U_w, Ht, xT_w, xT_b, X);
        CPCOMMIT();             // always commit (possibly empty) to keep group count

        if (t < HID) {
            const float* sU = (const float*)(smem + OFF_SU);
            const float* sX = (const float*)(smem + OFF_SX);
            const float z   = 1.0f / (1.0f + __expf(-(sX[t]       + sU[t])));
            const float r   = 1.0f / (1.0f + __expf(-(sX[t + 64]  + sU[t + 64])));
            const float htl = tanhf(sX[t + 128] + r * sU[t + 128]);
            const float hg  = z * htv + (1.0f - z) * htl;

            H_curr[(size_t)f * HID + t] = mv ? hg : 0.0f;
            if (mv) aggv += hg;
            if (t == 0) cnt += (int)mv;
        }
    }

    if (t < HID) g_partial_agg[b * HID + t] = aggv;
    if (t == 0)  g_partial_cnt[b] = cnt;
}

// ---------------------------------------------------------------------------
// Kernel 2: parallel partial reduction (16 slices x 64 h), MLP head, softmax.
// 1024 threads, deterministic (fixed-order fp sums; int smem atomic for count).
// ---------------------------------------------------------------------------
__global__ __launch_bounds__(1024) void finalize_kernel(
    const float* __restrict__ W1,
    const float* __restrict__ b1,
    const float* __restrict__ W2,
    const float* __restrict__ b2,
    float*       __restrict__ out)
{
    __shared__ float red[16][HID];
    __shared__ float sAgg[HID];
    __shared__ float sHid[HID];
    __shared__ int   scnt;

    const int t  = threadIdx.x;
    const int h  = t & 63;
    const int sl = t >> 6;          // 16 slices

    if (t == 0) scnt = 0;
    __syncthreads();

    float a = 0.0f;
    #pragma unroll 4
    for (int bb = sl; bb < NBLK; bb += 16) a += g_partial_agg[bb * HID + h];
    red[sl][h] = a;

    int c = 0;
    #pragma unroll
    for (int bb = t; bb < NBLK; bb += 1024) c += g_partial_cnt[bb];
    atomicAdd(&scnt, c);
    __syncthreads();

    if (t < HID) {
        float s = 0.0f;
        #pragma unroll
        for (int i = 0; i < 16; i++) s += red[i][t];
        const int total = scnt;
        if (t == 0) g_total_cnt = total;
        sAgg[t] = s / fmaxf((float)total, 1.0f);
    }
    __syncthreads();

    if (t < HID) {
        float acc = b1[t];
        #pragma unroll 8
        for (int k = 0; k < HID; k++) acc += sAgg[k] * W1[k * HID + t];
        sHid[t] = fmaxf(acc, 0.0f);
    }
    __syncthreads();

    if (t == 0) {
        float l0 = b2[0], l1 = b2[1];
        #pragma unroll 8
        for (int j = 0; j < HID; j++) {
            l0 += sHid[j] * W2[j * 2 + 0];
            l1 += sHid[j] * W2[j * 2 + 1];
        }
        const float mx = fmaxf(l0, l1);
        const float e0 = expf(l0 - mx), e1 = expf(l1 - mx);
        const float inv = 1.0f / (e0 + e1);
        out[0] = e0 * inv;
        out[1] = e1 * inv;
    }
}

// ---------------------------------------------------------------------------
// Kernel 3: if no feature masked, H_curr = Ht. Early-exits in common case.
// ---------------------------------------------------------------------------
__global__ void fixup_kernel(const float* __restrict__ Ht,
                             float*       __restrict__ H_curr)
{
    if (g_total_cnt > 0) return;
    const int total = NF * HID;
    for (int i = blockIdx.x * blockDim.x + threadIdx.x; i < total;
         i += gridDim.x * blockDim.x) {
        H_curr[i] = Ht[i];
    }
}

// ---------------------------------------------------------------------------
// Launch.  Inputs: tim, X, X_hap, mask, Ht, xT_w, xT_b, U_w, W1, b1, W2, b2.
// Output: [pred(2), H_curr(16384*64)] float32.
// ---------------------------------------------------------------------------
extern "C" void kernel_launch(void* const* d_in, const int* in_sizes, int n_in,
                              void* d_out, int out_size)
{
    const float* X     = (const float*)d_in[1];
    const void*  mask  = d_in[3];
    const float* Ht    = (const float*)d_in[4];
    const float* xT_w  = (const float*)d_in[5];
    const float* xT_b  = (const float*)d_in[6];
    const float* U_w   = (const float*)d_in[7];
    const float* W1    = (const float*)d_in[8];
    const float* b1    = (const float*)d_in[9];
    const float* W2    = (const float*)d_in[10];
    const float* b2    = (const float*)d_in[11];

    float* out    = (float*)d_out;
    float* H_curr = out + 2;

    cudaFuncSetAttribute(gru_main_kernel,
                         cudaFuncAttributeMaxDynamicSharedMemorySize, SMEM_TOTAL);

    gru_main_kernel<<<NBLK, TH, SMEM_TOTAL>>>(X, mask, Ht, xT_w, xT_b, U_w, H_curr);
    finalize_kernel<<<1, 1024>>>(W1, b1, W2, b2, out);
    fixup_kernel<<<64, 256>>>(Ht, H_curr);
}

// round 8
// speedup vs baseline: 1.6624x; 1.3879x over previous
#include <cuda_runtime.h>
#include <cuda_bf16.h>
#include <math.h>

// Problem constants
#define NF   16384
#define HID  64
#define TH   192          // 3*HID rows of U per feature
#define FPB  8            // features per block
#define NBLK (NF / FPB)   // 2048
#define BTH  256          // threads per block (8 warps, 24 rows/warp)

// Static scratch
__device__ float g_partial_agg[NBLK * HID];
__device__ int   g_partial_cnt[NBLK];
__device__ int   g_total_cnt;

__device__ __forceinline__ float dot4(float4 a, float4 b) {
    return a.x * b.x + a.y * b.y + a.z * b.z + a.w * b.w;
}

__device__ __forceinline__ bool mask_at(const void* mp, int mode, int f) {
    if (mode == 0) return ((const unsigned char*)mp)[f] != 0;
    if (mode == 1) return ((const int*)mp)[f] != 0;
    return ((const float*)mp)[f] != 0.0f;
}

// ---------------------------------------------------------------------------
// Kernel 1: per-feature GRU cell.
// 256 threads. Warp w owns rows [w*24, w*24+24). Within a warp, 8 lanes per
// row (q = lane&7 takes the q-th float4 of each 128B half-row), so every
// LDG.128 covers 4 rows x one full 128B line = ideal coalescing, no staging.
// Row dot = in-thread 8-float partial + 3x shfl.xor over the 8-lane group.
// ---------------------------------------------------------------------------
__global__ __launch_bounds__(BTH) void gru_main_kernel(
    const float* __restrict__ X,
    const void*  __restrict__ mask,
    const float* __restrict__ Ht,
    const float* __restrict__ xT_w,   // (F, 192, 1)
    const float* __restrict__ xT_b,   // (F, 192)
    const float* __restrict__ U_w,    // (F, 192, 64)
    float*       __restrict__ H_curr) // (F, 64)
{
    __shared__ float sHt[HID];
    __shared__ float sX[TH];
    __shared__ float sU[TH];
    __shared__ int   s_isf, s_isu8;

    const int t    = threadIdx.x;
    const int w    = t >> 5;
    const int l    = t & 31;
    const int q    = l & 7;           // float4 slot within half-row
    const int rsub = l >> 3;          // row within 4-row group
    const int rb   = w * 24 + rsub;   // base row for this thread

    // Parallel mask-format detection (2 loads/thread, resolved at 1st barrier).
    if (t == 0) { s_isf = 0; s_isu8 = 0; }
    __syncthreads();
    {
        const unsigned int*  mw = (const unsigned int*)mask;
        const unsigned char* mb = (const unsigned char*)mask;
        if (t < 64 && mw[t] == 0x3F800000u) atomicOr(&s_isf, 1);
        if ((t & 3) != 0 && mb[t] != 0)     atomicOr(&s_isu8, 1);
    }

    int   mode = 1;
    float aggv = 0.0f;
    int   cnt  = 0;

    #pragma unroll 1
    for (int j = 0; j < FPB; j++) {
        const int f = blockIdx.x * FPB + j;

        // Stage A: Ht + x_T into shared
        if (t < HID) sHt[t] = Ht[(size_t)f * HID + t];
        if (t < TH)
            sX[t] = fmaf(__ldcs(xT_w + (size_t)f * TH + t), X[f],
                         __ldcs(xT_b + (size_t)f * TH + t));
        __syncthreads();
        if (j == 0) mode = s_isf ? 2 : (s_isu8 ? 0 : 1);

        // Stage B: U dot rows (coalesced streaming loads)
        const float4* sHt4 = (const float4*)sHt;
        const float4  h0   = sHt4[q];          // cols [4q, 4q+4)
        const float4  h1   = sHt4[8 + q];      // cols [32+4q, 32+4q+4)
        const float4* Ub   = (const float4*)(U_w + (size_t)f * TH * HID);

        #pragma unroll
        for (int gg = 0; gg < 6; gg += 3) {
            const int r0 = rb + (gg + 0) * 4;
            const int r1 = rb + (gg + 1) * 4;
            const int r2 = rb + (gg + 2) * 4;
            float4 u00 = __ldcs(Ub + r0 * 16 + q);
            float4 u01 = __ldcs(Ub + r0 * 16 + 8 + q);
            float4 u10 = __ldcs(Ub + r1 * 16 + q);
            float4 u11 = __ldcs(Ub + r1 * 16 + 8 + q);
            float4 u20 = __ldcs(Ub + r2 * 16 + q);
            float4 u21 = __ldcs(Ub + r2 * 16 + 8 + q);

            float a0 = dot4(u00, h0) + dot4(u01, h1);
            float a1 = dot4(u10, h0) + dot4(u11, h1);
            float a2 = dot4(u20, h0) + dot4(u21, h1);

            a0 += __shfl_xor_sync(0xFFFFFFFFu, a0, 1);
            a1 += __shfl_xor_sync(0xFFFFFFFFu, a1, 1);
            a2 += __shfl_xor_sync(0xFFFFFFFFu, a2, 1);
            a0 += __shfl_xor_sync(0xFFFFFFFFu, a0, 2);
            a1 += __shfl_xor_sync(0xFFFFFFFFu, a1, 2);
            a2 += __shfl_xor_sync(0xFFFFFFFFu, a2, 2);
            a0 += __shfl_xor_sync(0xFFFFFFFFu, a0, 4);
            a1 += __shfl_xor_sync(0xFFFFFFFFu, a1, 4);
            a2 += __shfl_xor_sync(0xFFFFFFFFu, a2, 4);

            if (q == 0) {
                sU[r0] = a0;
                sU[r1] = a1;
                sU[r2] = a2;
            }
        }
        __syncthreads();

        // Stage C: gates
        if (t < HID) {
            const float z   = 1.0f / (1.0f + __expf(-(sX[t]       + sU[t])));
            const float r   = 1.0f / (1.0f + __expf(-(sX[t + 64]  + sU[t + 64])));
            const float htl = tanhf(sX[t + 128] + r * sU[t + 128]);
            const float hg  = z * sHt[t] + (1.0f - z) * htl;

            const bool mv = mask_at(mask, mode, f);
            __stcs(H_curr + (size_t)f * HID + t, mv ? hg : 0.0f);
            if (mv) aggv += hg;
            if (t == 0) cnt += (int)mv;
        }
        __syncthreads();   // protect sHt/sX/sU before next iteration
    }

    if (t < HID) g_partial_agg[blockIdx.x * HID + t] = aggv;
    if (t == 0)  g_partial_cnt[blockIdx.x] = cnt;
}

// ---------------------------------------------------------------------------
// Kernel 2: reduce partials (fully coalesced 16-slice), MLP head, softmax.
// ---------------------------------------------------------------------------
__global__ __launch_bounds__(1024) void finalize_kernel(
    const float* __restrict__ W1,
    const float* __restrict__ b1,
    const float* __restrict__ W2,
    const float* __restrict__ b2,
    float*       __restrict__ out)
{
    __shared__ float red[16][HID];
    __shared__ float sAgg[HID];
    __shared__ float sHid[HID];
    __shared__ int   scnt;

    const int t  = threadIdx.x;
    const int h  = t & 63;
    const int sl = t >> 6;

    if (t == 0) scnt = 0;
    __syncthreads();

    float a = 0.0f;
    #pragma unroll 8
    for (int bb = sl; bb < NBLK; bb += 16) a += g_partial_agg[bb * HID + h];
    red[sl][h] = a;

    int c = 0;
    for (int bb = t; bb < NBLK; bb += 1024) c += g_partial_cnt[bb];
    atomicAdd(&scnt, c);
    __syncthreads();

    if (t < HID) {
        float s = 0.0f;
        #pragma unroll
        for (int i = 0; i < 16; i++) s += red[i][t];
        const int total = scnt;
        if (t == 0) g_total_cnt = total;
        sAgg[t] = s / fmaxf((float)total, 1.0f);
    }
    __syncthreads();

    if (t < HID) {
        float acc = b1[t];
        #pragma unroll 8
        for (int k = 0; k < HID; k++) acc += sAgg[k] * W1[k * HID + t];
        sHid[t] = fmaxf(acc, 0.0f);
    }
    __syncthreads();

    if (t == 0) {
        float l0 = b2[0], l1 = b2[1];
        #pragma unroll 8
        for (int j = 0; j < HID; j++) {
            l0 += sHid[j] * W2[j * 2 + 0];
            l1 += sHid[j] * W2[j * 2 + 1];
        }
        const float mx = fmaxf(l0, l1);
        const float e0 = expf(l0 - mx), e1 = expf(l1 - mx);
        const float inv = 1.0f / (e0 + e1);
        out[0] = e0 * inv;
        out[1] = e1 * inv;
    }
}

// ---------------------------------------------------------------------------
// Kernel 3: if no feature masked, H_curr = Ht. Early-exits in common case.
// ---------------------------------------------------------------------------
__global__ void fixup_kernel(const float* __restrict__ Ht,
                             float*       __restrict__ H_curr)
{
    if (g_total_cnt > 0) return;
    const int total = NF * HID;
    for (int i = blockIdx.x * blockDim.x + threadIdx.x; i < total;
         i += gridDim.x * blockDim.x) {
        H_curr[i] = Ht[i];
    }
}

// ---------------------------------------------------------------------------
// Launch.  Inputs: tim, X, X_hap, mask, Ht, xT_w, xT_b, U_w, W1, b1, W2, b2.
// Output: [pred(2), H_curr(16384*64)] float32.
// ---------------------------------------------------------------------------
extern "C" void kernel_launch(void* const* d_in, const int* in_sizes, int n_in,
                              void* d_out, int out_size)
{
    const float* X     = (const float*)d_in[1];
    const void*  mask  = d_in[3];
    const float* Ht    = (const float*)d_in[4];
    const float* xT_w  = (const float*)d_in[5];
    const float* xT_b  = (const float*)d_in[6];
    const float* U_w   = (const float*)d_in[7];
    const float* W1    = (const float*)d_in[8];
    const float* b1    = (const float*)d_in[9];
    const float* W2    = (const float*)d_in[10];
    const float* b2    = (const float*)d_in[11];

    float* out    = (float*)d_out;
    float* H_curr = out + 2;

    gru_main_kernel<<<NBLK, BTH>>>(X, mask, Ht, xT_w, xT_b, U_w, H_curr);
    finalize_kernel<<<1, 1024>>>(W1, b1, W2, b2, out);
    fixup_kernel<<<64, 256>>>(Ht, H_curr);
}

// round 10
// speedup vs baseline: 2.0561x; 1.2368x over previous
#include <cuda_runtime.h>
#include <cuda_bf16.h>
#include <math.h>

// Problem constants
#define NF   16384
#define HID  64
#define TH   192          // 3*HID rows of U per feature
#define FPB  8            // features per block
#define NBLK (NF / FPB)   // 2048
#define BTH  256          // 8 warps; warp w owns gates [8w, 8w+8)

// Static scratch
__device__ float g_partial_agg[NBLK * HID];
__device__ int   g_partial_cnt[NBLK];
__device__ int   g_total_cnt;

__device__ __forceinline__ float dot4(float4 a, float4 b) {
    return a.x * b.x + a.y * b.y + a.z * b.z + a.w * b.w;
}

__device__ __forceinline__ bool mask_at(const void* mp, int mode, int f) {
    if (mode == 0) return ((const unsigned char*)mp)[f] != 0;
    if (mode == 1) return ((const int*)mp)[f] != 0;
    return ((const float*)mp)[f] != 0.0f;
}

__device__ __forceinline__ float red8(float v) {
    v += __shfl_xor_sync(0xFFFFFFFFu, v, 1);
    v += __shfl_xor_sync(0xFFFFFFFFu, v, 2);
    v += __shfl_xor_sync(0xFFFFFFFFu, v, 4);
    return v;
}

// ---------------------------------------------------------------------------
// Kernel 1: per-feature GRU cell — barrier-free main loop.
// Warp w owns gates g0 = 8w+rsub, g1 = g0+4 (rsub = lane>>3). Its 6 row-dots
// per feature are exactly the z/r/h rows of those two gates. 8 lanes per row
// (q = lane&7 reads the q-th float4 of each 128B half-row) -> every LDG.128
// is 4 rows x one full 128B line. After the 3-level shfl.xor all lanes hold
// all 6 dots; lanes q=0/q=1 finish gates g0/g1 entirely in registers.
// No shared memory, no __syncthreads in the loop; warps free-run.
// ---------------------------------------------------------------------------
__global__ __launch_bounds__(BTH) void gru_main_kernel(
    const float* __restrict__ X,
    const void*  __restrict__ mask,
    const float* __restrict__ Ht,
    const float* __restrict__ xT_w,   // (F, 192, 1)
    const float* __restrict__ xT_b,   // (F, 192)
    const float* __restrict__ U_w,    // (F, 192, 64)
    float*       __restrict__ H_curr) // (F, 64)
{
    __shared__ int s_isf, s_isu8;

    const int t    = threadIdx.x;
    const int w    = t >> 5;
    const int l    = t & 31;
    const int q    = l & 7;
    const int rsub = l >> 3;
    const int g0   = 8 * w + rsub;
    const int g1   = g0 + 4;
    const int g    = (q == 0) ? g0 : g1;   // gate owned by lanes q<2

    // mask-format detection: 0=u8, 1=i32, 2=f32 (one barrier, outside loop)
    if (t == 0) { s_isf = 0; s_isu8 = 0; }
    __syncthreads();
    {
        const unsigned int*  mw = (const unsigned int*)mask;
        const unsigned char* mb = (const unsigned char*)mask;
        if (t < 64 && mw[t] == 0x3F800000u) atomicOr(&s_isf, 1);
        if ((t & 3) != 0 && mb[t] != 0)     atomicOr(&s_isu8, 1);
    }
    __syncthreads();
    const int mode = s_isf ? 2 : (s_isu8 ? 0 : 1);

    float agg0 = 0.0f, agg1 = 0.0f;
    int   cnt  = 0;

    #pragma unroll 1
    for (int j = 0; j < FPB; j++) {
        const int f = blockIdx.x * FPB + j;

        // Ht slices for the dot (one broadcast-heavy LDG per warp half)
        const float4* Ht4 = (const float4*)(Ht + (size_t)f * HID);
        const float4  h0  = Ht4[q];
        const float4  h1  = Ht4[8 + q];

        // Gate-lane scalars (independent of U loads; lines shared in L1)
        float xz = 0.f, xr = 0.f, xh = 0.f, htg = 0.f;
        bool  mv = false;
        if (q < 2) {
            const float xf = X[f];
            const float* xw = xT_w + (size_t)f * TH;
            const float* xb = xT_b + (size_t)f * TH;
            xz  = fmaf(xw[g],       xf, xb[g]);
            xr  = fmaf(xw[g + 64],  xf, xb[g + 64]);
            xh  = fmaf(xw[g + 128], xf, xb[g + 128]);
            htg = Ht[(size_t)f * HID + g];
            mv  = mask_at(mask, mode, f);
        }

        // 12 front-batched streaming LDG.128 (rows of this warp's two gates)
        const float4* Ub = (const float4*)(U_w + (size_t)f * TH * HID);
        const float4 uA0 = __ldcs(Ub + (g0      ) * 16 + q);
        const float4 uB0 = __ldcs(Ub + (g0      ) * 16 + 8 + q);
        const float4 uA1 = __ldcs(Ub + (g0 +  64) * 16 + q);
        const float4 uB1 = __ldcs(Ub + (g0 +  64) * 16 + 8 + q);
        const float4 uA2 = __ldcs(Ub + (g0 + 128) * 16 + q);
        const float4 uB2 = __ldcs(Ub + (g0 + 128) * 16 + 8 + q);
        const float4 uA3 = __ldcs(Ub + (g1      ) * 16 + q);
        const float4 uB3 = __ldcs(Ub + (g1      ) * 16 + 8 + q);
        const float4 uA4 = __ldcs(Ub + (g1 +  64) * 16 + q);
        const float4 uB4 = __ldcs(Ub + (g1 +  64) * 16 + 8 + q);
        const float4 uA5 = __ldcs(Ub + (g1 + 128) * 16 + q);
        const float4 uB5 = __ldcs(Ub + (g1 + 128) * 16 + 8 + q);

        float d0 = dot4(uA0, h0) + dot4(uB0, h1);
        float d1 = dot4(uA1, h0) + dot4(uB1, h1);
        float d2 = dot4(uA2, h0) + dot4(uB2, h1);
        float d3 = dot4(uA3, h0) + dot4(uB3, h1);
        float d4 = dot4(uA4, h0) + dot4(uB4, h1);
        float d5 = dot4(uA5, h0) + dot4(uB5, h1);

        d0 = red8(d0); d1 = red8(d1); d2 = red8(d2);
        d3 = red8(d3); d4 = red8(d4); d5 = red8(d5);

        if (q < 2) {
            const float uz = (q == 0) ? d0 : d3;
            const float ur = (q == 0) ? d1 : d4;
            const float uh = (q == 0) ? d2 : d5;

            const float z   = 1.0f / (1.0f + __expf(-(xz + uz)));
            const float r   = 1.0f / (1.0f + __expf(-(xr + ur)));
            const float htl = tanhf(xh + r * uh);
            const float hg  = z * htg + (1.0f - z) * htl;

            __stcs(H_curr + (size_t)f * HID + g, mv ? hg : 0.0f);
            const float add = mv ? hg : 0.0f;
            if (q == 0) agg0 += add; else agg1 += add;
            if (t == 0) cnt += (int)mv;
        }
    }

    if (q == 0) g_partial_agg[blockIdx.x * HID + g0] = agg0;
    if (q == 1) g_partial_agg[blockIdx.x * HID + g1] = agg1;
    if (t == 0) g_partial_cnt[blockIdx.x] = cnt;
}

// ---------------------------------------------------------------------------
// Kernel 2: reduce partials (coalesced 16-slice), MLP head, softmax.
// ---------------------------------------------------------------------------
__global__ __launch_bounds__(1024) void finalize_kernel(
    const float* __restrict__ W1,
    const float* __restrict__ b1,
    const float* __restrict__ W2,
    const float* __restrict__ b2,
    float*       __restrict__ out)
{
    __shared__ float red[16][HID];
    __shared__ float sAgg[HID];
    __shared__ float sHid[HID];
    __shared__ int   scnt;

    const int t  = threadIdx.x;
    const int h  = t & 63;
    const int sl = t >> 6;

    if (t == 0) scnt = 0;
    __syncthreads();

    float a = 0.0f;
    #pragma unroll 8
    for (int bb = sl; bb < NBLK; bb += 16) a += g_partial_agg[bb * HID + h];
    red[sl][h] = a;

    int c = 0;
    for (int bb = t; bb < NBLK; bb += 1024) c += g_partial_cnt[bb];
    atomicAdd(&scnt, c);
    __syncthreads();

    if (t < HID) {
        float s = 0.0f;
        #pragma unroll
        for (int i = 0; i < 16; i++) s += red[i][t];
        const int total = scnt;
        if (t == 0) g_total_cnt = total;
        sAgg[t] = s / fmaxf((float)total, 1.0f);
    }
    __syncthreads();

    if (t < HID) {
        float acc = b1[t];
        #pragma unroll 8
        for (int k = 0; k < HID; k++) acc += sAgg[k] * W1[k * HID + t];
        sHid[t] = fmaxf(acc, 0.0f);
    }
    __syncthreads();

    if (t == 0) {
        float l0 = b2[0], l1 = b2[1];
        #pragma unroll 8
        for (int j = 0; j < HID; j++) {
            l0 += sHid[j] * W2[j * 2 + 0];
            l1 += sHid[j] * W2[j * 2 + 1];
        }
        const float mx = fmaxf(l0, l1);
        const float e0 = expf(l0 - mx), e1 = expf(l1 - mx);
        const float inv = 1.0f / (e0 + e1);
        out[0] = e0 * inv;
        out[1] = e1 * inv;
    }
}

// ---------------------------------------------------------------------------
// Kernel 3: if no feature masked, H_curr = Ht. Early-exits in common case.
// ---------------------------------------------------------------------------
__global__ void fixup_kernel(const float* __restrict__ Ht,
                             float*       __restrict__ H_curr)
{
    if (g_total_cnt > 0) return;
    const int total = NF * HID;
    for (int i = blockIdx.x * blockDim.x + threadIdx.x; i < total;
         i += gridDim.x * blockDim.x) {
        H_curr[i] = Ht[i];
    }
}

// ---------------------------------------------------------------------------
// Launch.  Inputs: tim, X, X_hap, mask, Ht, xT_w, xT_b, U_w, W1, b1, W2, b2.
// Output: [pred(2), H_curr(16384*64)] float32.
// ---------------------------------------------------------------------------
extern "C" void kernel_launch(void* const* d_in, const int* in_sizes, int n_in,
                              void* d_out, int out_size)
{
    const float* X     = (const float*)d_in[1];
    const void*  mask  = d_in[3];
    const float* Ht    = (const float*)d_in[4];
    const float* xT_w  = (const float*)d_in[5];
    const float* xT_b  = (const float*)d_in[6];
    const float* U_w   = (const float*)d_in[7];
    const float* W1    = (const float*)d_in[8];
    const float* b1    = (const float*)d_in[9];
    const float* W2    = (const float*)d_in[10];
    const float* b2    = (const float*)d_in[11];

    float* out    = (float*)d_out;
    float* H_curr = out + 2;

    gru_main_kernel<<<NBLK, BTH>>>(X, mask, Ht, xT_w, xT_b, U_w, H_curr);
    finalize_kernel<<<1, 1024>>>(W1, b1, W2, b2, out);
    fixup_kernel<<<64, 256>>>(Ht, H_curr);
}